// round 9
// baseline (speedup 1.0000x reference)
#include <cuda_runtime.h>
#include <cuda_bf16.h>
#include <math.h>

// Problem constants (from reference): N=100000, H=128, E=500000, G=3
#define MAX_E      600000
#define CHUNK      128
#define MAX_CHUNKS ((MAX_E + CHUNK - 1) / CHUNK)

__device__ int d_perm[MAX_E];
__device__ int d_chunkCnt[MAX_CHUNKS * 3];
__device__ int d_chunkOff[MAX_CHUNKS * 3];
__device__ int d_groupStart[4];
__device__ int d_tileBase[4];

// ---- packed f32x2 helpers (Blackwell sm_100+) ------------------------------
__device__ __forceinline__ unsigned long long pack2(float x) {
    unsigned long long r;
    asm("mov.b64 %0, {%1, %1};" : "=l"(r) : "f"(x));
    return r;
}
__device__ __forceinline__ void ffma2(unsigned long long& d,
                                      unsigned long long a,
                                      unsigned long long b) {
    asm("fma.rn.f32x2 %0, %1, %2, %0;" : "+l"(d) : "l"(a), "l"(b));
}
__device__ __forceinline__ float2 unpack2(unsigned long long v) {
    float2 f;
    asm("mov.b64 {%0, %1}, %2;" : "=f"(f.x), "=f"(f.y) : "l"(v));
    return f;
}

// ---------------------------------------------------------------------------
// Stable 3-way partition of edge indices by group (64-edge tiles).
// ---------------------------------------------------------------------------

__global__ void k_count(const int* __restrict__ groups, int E, int nChunks) {
    int c = blockIdx.x * blockDim.x + threadIdx.x;
    if (c >= nChunks) return;
    int c0 = 0, c1 = 0, c2 = 0;
    int s = c * CHUNK, e = s + CHUNK; if (e > E) e = E;
    for (int i = s; i < e; i++) {
        int g = groups[i];
        c0 += (g == 0); c1 += (g == 1); c2 += (g == 2);
    }
    d_chunkCnt[c * 3 + 0] = c0;
    d_chunkCnt[c * 3 + 1] = c1;
    d_chunkCnt[c * 3 + 2] = c2;
}

#define SCAN_T 512

__global__ void k_scan(int nChunks) {
    __shared__ int sv[SCAN_T];
    __shared__ int gtot[3];
    __shared__ int gs[4];
    int tid = threadIdx.x;
    int per = (nChunks + SCAN_T - 1) / SCAN_T;
    int c0 = tid * per;
    int c1 = c0 + per; if (c1 > nChunks) c1 = nChunks;
    if (c0 > nChunks) c0 = nChunks;

    int t[3] = {0, 0, 0};
    for (int c = c0; c < c1; c++) {
        t[0] += d_chunkCnt[c * 3 + 0];
        t[1] += d_chunkCnt[c * 3 + 1];
        t[2] += d_chunkCnt[c * 3 + 2];
    }
    int base[3];
    for (int g = 0; g < 3; g++) {
        sv[tid] = t[g];
        __syncthreads();
        for (int off = 1; off < SCAN_T; off <<= 1) {
            int v = (tid >= off) ? sv[tid - off] : 0;
            __syncthreads();
            sv[tid] += v;
            __syncthreads();
        }
        base[g] = sv[tid] - t[g];
        if (tid == SCAN_T - 1) gtot[g] = sv[tid];
        __syncthreads();
    }
    if (tid == 0) {
        gs[0] = 0;
        gs[1] = gtot[0];
        gs[2] = gtot[0] + gtot[1];
        gs[3] = gtot[0] + gtot[1] + gtot[2];
        int tb = 0;
        for (int g = 0; g < 3; g++) {
            d_groupStart[g] = gs[g];
            d_tileBase[g] = tb;
            tb += (gtot[g] + 63) >> 6;     // 64-edge tiles
        }
        d_groupStart[3] = gs[3];
        d_tileBase[3] = tb;
    }
    __syncthreads();
    int run[3];
    for (int g = 0; g < 3; g++) run[g] = gs[g] + base[g];
    for (int c = c0; c < c1; c++) {
        for (int g = 0; g < 3; g++) {
            d_chunkOff[c * 3 + g] = run[g];
            run[g] += d_chunkCnt[c * 3 + g];
        }
    }
}

__global__ void k_scatter(const int* __restrict__ groups, int E, int nChunks) {
    int c = blockIdx.x * blockDim.x + threadIdx.x;
    if (c >= nChunks) return;
    int o0 = d_chunkOff[c * 3 + 0];
    int o1 = d_chunkOff[c * 3 + 1];
    int o2 = d_chunkOff[c * 3 + 2];
    int s = c * CHUNK, e = s + CHUNK; if (e > E) e = E;
    for (int i = s; i < e; i++) {
        int g = groups[i];
        int p = (g == 0) ? o0++ : (g == 1) ? o1++ : o2++;
        d_perm[p] = i;
    }
}

// ---------------------------------------------------------------------------
// Main fused kernel. One CTA per 64-edge tile, 256 threads = 32tx x 8ty.
// Thread tile: GEMM1 8 rows x 4 cols (cols tx*4..+3), GEMM2 8 rows x 2 cols.
// Warp == one ty => A-operand smem loads are warp-broadcast (free).
// Static smem union (phase2 max 38.1 KB), no attribute calls.
// ---------------------------------------------------------------------------

__global__ __launch_bounds__(256, 3) void k_main(
    const float* __restrict__ emb, const int* __restrict__ edges,
    const float* __restrict__ W1, const float* __restrict__ b1,
    const float* __restrict__ lng, const float* __restrict__ lnb,
    const float* __restrict__ W2, const float* __restrict__ b2,
    const float* __restrict__ W3, const float* __restrict__ b3,
    float* __restrict__ out)
{
    __shared__ __align__(16) union {
        struct { float ee[64 * 36]; float w1[32 * 132]; } p1;  // 26.1 KB
        struct { float h[64 * 132]; float w2[16 * 68]; } p2;   // 38.1 KB
    } sm;
    __shared__ int sU[64], sV[64];

    int b = blockIdx.x;
    if (b >= d_tileBase[3]) return;
    int g = (b >= d_tileBase[1]) + (b >= d_tileBase[2]);
    int tileInG = b - d_tileBase[g];
    int tileStart = d_groupStart[g] + tileInG * 64;
    int nE = d_groupStart[g + 1] - tileStart;
    if (nE > 64) nE = 64;

    int tid = threadIdx.x;
    if (tid < 64) {
        int u = 0, v = 0;
        if (tid < nE) {
            int e = d_perm[tileStart + tid];
            u = edges[2 * e];
            v = edges[2 * e + 1];
        }
        sU[tid] = u; sV[tid] = v;
    }
    __syncthreads();

    const int tx = tid & 31, ty = tid >> 5;   // 32 x 8; warp == one ty

    // acc2[i][p]: rows ty*8+i (i 0..7); p 0,1 -> cols tx*4+{0,1},{2,3}
    unsigned long long acc2[8][2];
#pragma unroll
    for (int i = 0; i < 8; i++) { acc2[i][0] = 0ull; acc2[i][1] = 0ull; }

    const float* W1g = W1 + (size_t)g * 256 * 128;

    // ---- GEMM1: [64,256] x [256,128], BK = 32 ----
    for (int kb = 0; kb < 256; kb += 32) {
        // ee tile: 512 float4 (2 per thread)
#pragma unroll
        for (int t = 0; t < 2; t++) {
            int idx = tid + t * 256;        // 0..511
            int r = idx >> 3, q = idx & 7;  // row 0..63, q 0..7
            int node = (kb < 128) ? sU[r] : sV[r];
            int cb = (kb & 127) + q * 4;
            float4 val = *(const float4*)(emb + (size_t)node * 128 + cb);
            *(float4*)(&sm.p1.ee[r * 36 + q * 4]) = val;
        }
        // W1 tile: 1024 float4 (4 per thread)
#pragma unroll
        for (int t = 0; t < 4; t++) {
            int idx = tid + t * 256;
            int rr = idx >> 5, q = idx & 31;
            float4 val = *(const float4*)(W1g + (size_t)(kb + rr) * 128 + q * 4);
            *(float4*)(&sm.p1.w1[rr * 132 + q * 4]) = val;
        }
        __syncthreads();

#pragma unroll
        for (int kk4 = 0; kk4 < 32; kk4 += 4) {
            // B operands for 4 k-steps (each: this thread's 4 cols)
            ulonglong2 bv[4];
#pragma unroll
            for (int u = 0; u < 4; u++)
                bv[u] = *(const ulonglong2*)(&sm.p1.w1[(kk4 + u) * 132 + tx * 4]);
            // Two 4-row halves to keep A staging small
#pragma unroll
            for (int half = 0; half < 2; half++) {
                float4 a4[4];
#pragma unroll
                for (int i = 0; i < 4; i++)
                    a4[i] = *(const float4*)(&sm.p1.ee[(ty * 8 + half * 4 + i) * 36 + kk4]);
                const float* ap = reinterpret_cast<const float*>(a4);
#pragma unroll
                for (int u = 0; u < 4; u++) {
#pragma unroll
                    for (int i = 0; i < 4; i++) {
                        unsigned long long pa = pack2(ap[i * 4 + u]);
                        int row = half * 4 + i;
                        ffma2(acc2[row][0], pa, bv[u].x);
                        ffma2(acc2[row][1], pa, bv[u].y);
                    }
                }
            }
        }
        __syncthreads();
    }

    // ---- bias + LayerNorm + exact GELU, write h to smem ----
    float bb1[4], lgv[4], lbv[4];
#pragma unroll
    for (int j = 0; j < 4; j++) {
        int o = tx * 4 + j;
        bb1[j] = b1[g * 128 + o];
        lgv[j] = lng[g * 128 + o];
        lbv[j] = lnb[g * 128 + o];
    }
#pragma unroll
    for (int i = 0; i < 8; i++) {
        float hv[4];
        float2 f0 = unpack2(acc2[i][0]);
        float2 f1 = unpack2(acc2[i][1]);
        hv[0] = f0.x; hv[1] = f0.y; hv[2] = f1.x; hv[3] = f1.y;
        float s = 0.f, s2 = 0.f;
#pragma unroll
        for (int j = 0; j < 4; j++) {
            float h = hv[j] + bb1[j];
            hv[j] = h;
            s += h; s2 += h * h;
        }
#pragma unroll
        for (int m = 1; m < 32; m <<= 1) {   // full-warp reduce: 32 lanes = row
            s  += __shfl_xor_sync(0xffffffffu, s,  m);
            s2 += __shfl_xor_sync(0xffffffffu, s2, m);
        }
        float mu  = s * (1.f / 128.f);
        float var = s2 * (1.f / 128.f) - mu * mu;
        float inv = rsqrtf(var + 1e-5f);
        float4 outA;
        float* oa = reinterpret_cast<float*>(&outA);
#pragma unroll
        for (int j = 0; j < 4; j++) {
            float hn = (hv[j] - mu) * inv * lgv[j] + lbv[j];
            oa[j] = hn * normcdff(hn);       // exact gelu: x * Phi(x)
        }
        int row = ty * 8 + i;
        *(float4*)(&sm.p2.h[row * 132 + tx * 4]) = outA;
    }

    // ---- GEMM2: [64,128] x [128,64], BK = 16; thread tile 8 rows x 2 cols --
    const float* W2g = W2 + (size_t)g * 128 * 64;
    unsigned long long c2[8];
#pragma unroll
    for (int i = 0; i < 8; i++) c2[i] = 0ull;

    for (int kb = 0; kb < 128; kb += 16) {
        __syncthreads();  // protects w2 reuse; first iter also orders h writes
        {
            // w2 tile: 16 rows x 16 float4 = 256 float4 (1 per thread)
            int rr = tid >> 4, q = tid & 15;
            float4 val = *(const float4*)(W2g + (size_t)(kb + rr) * 64 + q * 4);
            *(float4*)(&sm.p2.w2[rr * 68 + q * 4]) = val;
        }
        __syncthreads();

#pragma unroll
        for (int kk4 = 0; kk4 < 16; kk4 += 4) {
            unsigned long long bw[4];
#pragma unroll
            for (int u = 0; u < 4; u++)
                bw[u] = *(const unsigned long long*)(&sm.p2.w2[(kk4 + u) * 68 + tx * 2]);
#pragma unroll
            for (int half = 0; half < 2; half++) {
                float4 a4[4];
#pragma unroll
                for (int i = 0; i < 4; i++)
                    a4[i] = *(const float4*)(&sm.p2.h[(ty * 8 + half * 4 + i) * 132 + kb + kk4]);
                const float* ap = reinterpret_cast<const float*>(a4);
#pragma unroll
                for (int u = 0; u < 4; u++) {
#pragma unroll
                    for (int i = 0; i < 4; i++) {
                        unsigned long long pa = pack2(ap[i * 4 + u]);
                        ffma2(c2[half * 4 + i], pa, bw[u]);
                    }
                }
            }
        }
    }

    // ---- bias + GELU + dot W3 + b3, full-warp reduce, write ----
    float bb2[2], w3v[2];
#pragma unroll
    for (int j = 0; j < 2; j++) {
        bb2[j] = b2[g * 64 + tx * 2 + j];
        w3v[j] = W3[g * 64 + tx * 2 + j];
    }
    float b3v = b3[g];
#pragma unroll
    for (int i = 0; i < 8; i++) {
        float2 f0 = unpack2(c2[i]);
        float x0 = f0.x + bb2[0];
        float x1 = f0.y + bb2[1];
        float p = fmaf(x0 * normcdff(x0), w3v[0], 0.f);
        p = fmaf(x1 * normcdff(x1), w3v[1], p);
#pragma unroll
        for (int m = 1; m < 32; m <<= 1)
            p += __shfl_xor_sync(0xffffffffu, p, m);
        int r = ty * 8 + i;
        if (tx == 0 && r < nE) out[tileStart + r] = p + b3v;
    }
}

// ---------------------------------------------------------------------------

extern "C" void kernel_launch(void* const* d_in, const int* in_sizes, int n_in,
                              void* d_out, int out_size) {
    const float* emb    = (const float*)d_in[0];
    const int*   edges  = (const int*)d_in[1];
    const int*   groups = (const int*)d_in[2];
    const float* W1     = (const float*)d_in[3];
    const float* b1     = (const float*)d_in[4];
    const float* lng    = (const float*)d_in[5];
    const float* lnb    = (const float*)d_in[6];
    const float* W2     = (const float*)d_in[7];
    const float* b2     = (const float*)d_in[8];
    const float* W3     = (const float*)d_in[9];
    const float* b3     = (const float*)d_in[10];
    float* out = (float*)d_out;

    int E = in_sizes[2];
    int nChunks = (E + CHUNK - 1) / CHUNK;

    k_count<<<(nChunks + 255) / 256, 256>>>(groups, E, nChunks);
    k_scan<<<1, SCAN_T>>>(nChunks);
    k_scatter<<<(nChunks + 255) / 256, 256>>>(groups, E, nChunks);

    int maxTiles = (E + 63) / 64 + 3;
    k_main<<<maxTiles, 256>>>(emb, edges, W1, b1, lng, lnb, W2, b2, W3, b3, out);
}

// round 12
// speedup vs baseline: 1.2108x; 1.2108x over previous
#include <cuda_runtime.h>
#include <cuda_bf16.h>
#include <math.h>
#include <stdint.h>

// Problem constants: N=100000, H=128, E=500000, G=3
#define MAX_E      600000
#define MAX_NODES  100608
#define CHUNK      128
#define MAX_CHUNKS ((MAX_E + CHUNK - 1) / CHUNK)

__device__ int d_perm[MAX_E];
__device__ int d_chunkCnt[MAX_CHUNKS * 3];
__device__ int d_chunkOff[MAX_CHUNKS * 3];
__device__ int d_groupStart[4];
__device__ int d_tileBase[4];

// bf16 hi/lo split tables (prep kernels fill these every launch)
__device__ unsigned short d_emb_hi[MAX_NODES * 128];
__device__ unsigned short d_emb_lo[MAX_NODES * 128];
__device__ unsigned short d_w1t_hi[3 * 128 * 256];   // [g][n=128][k=256]
__device__ unsigned short d_w1t_lo[3 * 128 * 256];
__device__ unsigned short d_w2t_hi[3 * 64 * 128];    // [g][n=64][k=128]
__device__ unsigned short d_w2t_lo[3 * 64 * 128];

// ======================= helpers ============================================
__device__ __forceinline__ uint32_t smem_u32(const void* p) {
    uint32_t a;
    asm("{ .reg .u64 t; cvta.to.shared.u64 t, %1; cvt.u32.u64 %0, t; }"
        : "=r"(a) : "l"(p));
    return a;
}
__device__ __forceinline__ void ldsm4(uint32_t& r0, uint32_t& r1,
                                      uint32_t& r2, uint32_t& r3, uint32_t a) {
    asm volatile("ldmatrix.sync.aligned.m8n8.x4.shared.b16 {%0,%1,%2,%3}, [%4];"
        : "=r"(r0), "=r"(r1), "=r"(r2), "=r"(r3) : "r"(a));
}
__device__ __forceinline__ void mma_bf16(float* d, const uint32_t* a,
                                         uint32_t b0, uint32_t b1) {
    asm volatile("mma.sync.aligned.m16n8k16.row.col.f32.bf16.bf16.f32 "
        "{%0,%1,%2,%3}, {%4,%5,%6,%7}, {%8,%9}, {%0,%1,%2,%3};"
        : "+f"(d[0]), "+f"(d[1]), "+f"(d[2]), "+f"(d[3])
        : "r"(a[0]), "r"(a[1]), "r"(a[2]), "r"(a[3]), "r"(b0), "r"(b1));
}
__device__ __forceinline__ uint32_t pack_bf16x2(float x, float y) {
    __nv_bfloat162 v = __floats2bfloat162_rn(x, y);
    return *reinterpret_cast<uint32_t*>(&v);
}

// ======================= partition (128-edge tiles) =========================
__global__ void k_count(const int* __restrict__ groups, int E, int nChunks) {
    int c = blockIdx.x * blockDim.x + threadIdx.x;
    if (c >= nChunks) return;
    int c0 = 0, c1 = 0, c2 = 0;
    int s = c * CHUNK, e = s + CHUNK; if (e > E) e = E;
    for (int i = s; i < e; i++) {
        int g = groups[i];
        c0 += (g == 0); c1 += (g == 1); c2 += (g == 2);
    }
    d_chunkCnt[c * 3 + 0] = c0; d_chunkCnt[c * 3 + 1] = c1; d_chunkCnt[c * 3 + 2] = c2;
}

#define SCAN_T 512
__global__ void k_scan(int nChunks) {
    __shared__ int sv[SCAN_T]; __shared__ int gtot[3]; __shared__ int gs[4];
    int tid = threadIdx.x;
    int per = (nChunks + SCAN_T - 1) / SCAN_T;
    int c0 = tid * per, c1 = c0 + per;
    if (c1 > nChunks) c1 = nChunks;
    if (c0 > nChunks) c0 = nChunks;
    int t[3] = {0, 0, 0};
    for (int c = c0; c < c1; c++) {
        t[0] += d_chunkCnt[c * 3]; t[1] += d_chunkCnt[c * 3 + 1]; t[2] += d_chunkCnt[c * 3 + 2];
    }
    int base[3];
    for (int g = 0; g < 3; g++) {
        sv[tid] = t[g];
        __syncthreads();
        for (int off = 1; off < SCAN_T; off <<= 1) {
            int v = (tid >= off) ? sv[tid - off] : 0;
            __syncthreads(); sv[tid] += v; __syncthreads();
        }
        base[g] = sv[tid] - t[g];
        if (tid == SCAN_T - 1) gtot[g] = sv[tid];
        __syncthreads();
    }
    if (tid == 0) {
        gs[0] = 0; gs[1] = gtot[0]; gs[2] = gtot[0] + gtot[1]; gs[3] = gs[2] + gtot[2];
        int tb = 0;
        for (int g = 0; g < 3; g++) {
            d_groupStart[g] = gs[g]; d_tileBase[g] = tb;
            tb += (gtot[g] + 127) >> 7;
        }
        d_groupStart[3] = gs[3]; d_tileBase[3] = tb;
    }
    __syncthreads();
    int run[3];
    for (int g = 0; g < 3; g++) run[g] = gs[g] + base[g];
    for (int c = c0; c < c1; c++)
        for (int g = 0; g < 3; g++) { d_chunkOff[c * 3 + g] = run[g]; run[g] += d_chunkCnt[c * 3 + g]; }
}

__global__ void k_scatter(const int* __restrict__ groups, int E, int nChunks) {
    int c = blockIdx.x * blockDim.x + threadIdx.x;
    if (c >= nChunks) return;
    int o0 = d_chunkOff[c * 3], o1 = d_chunkOff[c * 3 + 1], o2 = d_chunkOff[c * 3 + 2];
    int s = c * CHUNK, e = s + CHUNK; if (e > E) e = E;
    for (int i = s; i < e; i++) {
        int g = groups[i];
        int p = (g == 0) ? o0++ : (g == 1) ? o1++ : o2++;
        d_perm[p] = i;
    }
}

// =========================== bf16 split preps ===============================
__device__ __forceinline__ void split_bf16(float x, unsigned short& h, unsigned short& l) {
    __nv_bfloat16 hb = __float2bfloat16(x);
    float hf = __bfloat162float(hb);
    __nv_bfloat16 lb = __float2bfloat16(x - hf);
    h = __bfloat16_as_ushort(hb); l = __bfloat16_as_ushort(lb);
}
__global__ void k_split_emb(const float* __restrict__ emb, int total) {
    int i = blockIdx.x * blockDim.x + threadIdx.x;
    if (i >= total) return;
    split_bf16(emb[i], d_emb_hi[i], d_emb_lo[i]);
}
__global__ void k_split_w1(const float* __restrict__ W1) {
    int i = blockIdx.x * blockDim.x + threadIdx.x;
    if (i >= 3 * 256 * 128) return;
    int g = i / (256 * 128), r = i % (256 * 128);
    int d = r / 128, h = r % 128;
    int dst = (g * 128 + h) * 256 + d;
    split_bf16(W1[i], d_w1t_hi[dst], d_w1t_lo[dst]);
}
__global__ void k_split_w2(const float* __restrict__ W2) {
    int i = blockIdx.x * blockDim.x + threadIdx.x;
    if (i >= 3 * 128 * 64) return;
    int g = i / (128 * 64), r = i % (128 * 64);
    int k = r / 64, n = r % 64;
    int dst = (g * 64 + n) * 128 + k;
    split_bf16(W2[i], d_w2t_hi[dst], d_w2t_lo[dst]);
}

// =============================== main kernel ================================
// 128-edge tile per CTA, 256 threads = 8 warps; warp w owns rows w*16..w*16+15.
// GEMM1: mma.sync bf16 (3-product fp32-split emulation), K=256 in 8 chunks.
// LN+GELU epilogue keeps h in registers as GEMM2 A-fragments (layout identity).
// Smem rows padded +8 bf16 (stride 80B / 272B) => LDSM conflict-free.

#define AST 40     // A/B1 padded row stride in bf16 (32+8)
#define BST2 136   // B2 padded row stride in bf16 (128+8)

__global__ __launch_bounds__(256) void k_main(
    const int* __restrict__ edges,
    const float* __restrict__ b1, const float* __restrict__ lng,
    const float* __restrict__ lnb, const float* __restrict__ b2,
    const float* __restrict__ W3, const float* __restrict__ b3,
    float* __restrict__ out)
{
    __shared__ __align__(16) union {
        struct {
            unsigned short Ah[128 * AST]; unsigned short Al[128 * AST];
            unsigned short Bh[128 * AST]; unsigned short Bl[128 * AST];
        } p1;                                             // 40960 B
        struct {
            unsigned short B2h[64 * BST2]; unsigned short B2l[64 * BST2];
        } p2;                                             // 34816 B
    } sm;
    __shared__ int sU[128], sV[128];
    __shared__ float s_b1[128], s_lng[128], s_lnb[128];
    __shared__ float s_b2[64], s_w3[64];

    int b = blockIdx.x;
    if (b >= d_tileBase[3]) return;
    int g = (b >= d_tileBase[1]) + (b >= d_tileBase[2]);
    int tileStart = d_groupStart[g] + (b - d_tileBase[g]) * 128;
    int nE = d_groupStart[g + 1] - tileStart;
    if (nE > 128) nE = 128;

    int tid = threadIdx.x;
    int w = tid >> 5, L = tid & 31;
    int lg = L >> 2, lt = L & 3;          // groupID, thread-in-group
    int m8 = L >> 3, r8 = L & 7;          // ldmatrix quad index, row-in-quad

    if (tid < 128) {
        int u = 0, v = 0;
        if (tid < nE) {
            int e = d_perm[tileStart + tid];
            u = edges[2 * e]; v = edges[2 * e + 1];
        }
        sU[tid] = u; sV[tid] = v;
        s_b1[tid]  = b1[g * 128 + tid];
        s_lng[tid] = lng[g * 128 + tid];
        s_lnb[tid] = lnb[g * 128 + tid];
    }
    if (tid < 64) { s_b2[tid] = b2[g * 64 + tid]; s_w3[tid] = W3[g * 64 + tid]; }
    __syncthreads();

    const unsigned short* w1h = d_w1t_hi + (size_t)g * 128 * 256;
    const unsigned short* w1l = d_w1t_lo + (size_t)g * 128 * 256;

    // ---- GEMM1: D1[128,128] ------------------------------------------------
    float d1[16][4];
#pragma unroll
    for (int n = 0; n < 16; n++)
#pragma unroll
        for (int j = 0; j < 4; j++) d1[n][j] = 0.f;

    // ldmatrix lane-address components (A: row quads / k-halves; B: n / k)
    uint32_t baseAh = smem_u32(sm.p1.Ah), baseAl = smem_u32(sm.p1.Al);
    uint32_t baseBh = smem_u32(sm.p1.Bh), baseBl = smem_u32(sm.p1.Bl);
    uint32_t aRow = (uint32_t)(w * 16 + r8 + (m8 & 1) * 8);
    uint32_t aK   = (uint32_t)((m8 >> 1) * 8);
    uint32_t bN   = (uint32_t)(r8 + (m8 >> 1) * 8);
    uint32_t bK   = (uint32_t)((m8 & 1) * 8);

    for (int cb = 0; cb < 8; cb++) {
        int kb = cb * 32;
        // fill A (ee chunk): 1024 uint4 (4/thread), hi then lo
#pragma unroll
        for (int t = 0; t < 4; t++) {
            int idx = tid + t * 256;
            int buf = idx >> 9, i = idx & 511;
            int row = i >> 2, q = i & 3;
            int node = (kb < 128) ? sU[row] : sV[row];
            const unsigned short* src = (buf ? d_emb_lo : d_emb_hi)
                + (size_t)node * 128 + (kb & 127) + q * 8;
            unsigned short* dst = (buf ? sm.p1.Al : sm.p1.Ah) + row * AST + q * 8;
            *(uint4*)dst = *(const uint4*)src;
        }
        // fill B (W1T chunk): 1024 uint4 (4/thread)
#pragma unroll
        for (int t = 0; t < 4; t++) {
            int idx = tid + t * 256;
            int buf = idx >> 9, i = idx & 511;
            int n = i >> 2, q = i & 3;
            const unsigned short* src = (buf ? w1l : w1h) + (size_t)n * 256 + kb + q * 8;
            unsigned short* dst = (buf ? sm.p1.Bl : sm.p1.Bh) + n * AST + q * 8;
            *(uint4*)dst = *(const uint4*)src;
        }
        __syncthreads();

#pragma unroll
        for (int ks = 0; ks < 2; ks++) {
            uint32_t aoff = (aRow * AST + ks * 16 + aK) * 2;
            uint32_t ah[4], al[4];
            ldsm4(ah[0], ah[1], ah[2], ah[3], baseAh + aoff);
            ldsm4(al[0], al[1], al[2], al[3], baseAl + aoff);
#pragma unroll
            for (int p = 0; p < 8; p++) {
                uint32_t boff = ((16 * p + bN) * AST + ks * 16 + bK) * 2;
                uint32_t bh0, bh1, bh2, bh3, bl0, bl1, bl2, bl3;
                ldsm4(bh0, bh1, bh2, bh3, baseBh + boff);
                ldsm4(bl0, bl1, bl2, bl3, baseBl + boff);
                mma_bf16(d1[2 * p],     ah, bh0, bh1);
                mma_bf16(d1[2 * p],     ah, bl0, bl1);
                mma_bf16(d1[2 * p],     al, bh0, bh1);
                mma_bf16(d1[2 * p + 1], ah, bh2, bh3);
                mma_bf16(d1[2 * p + 1], ah, bl2, bl3);
                mma_bf16(d1[2 * p + 1], al, bh2, bh3);
            }
        }
        __syncthreads();
    }

    // ---- stage B2 (W2T full K) into smem (phase-1 buffers now dead) -------
    {
        const unsigned short* w2h = d_w2t_hi + (size_t)g * 64 * 128;
        const unsigned short* w2l = d_w2t_lo + (size_t)g * 64 * 128;
#pragma unroll
        for (int t = 0; t < 8; t++) {
            int idx = tid + t * 256;
            int buf = idx >> 10, i = idx & 1023;
            int n = i >> 4, q = i & 15;
            const unsigned short* src = (buf ? w2l : w2h) + (size_t)n * 128 + q * 8;
            unsigned short* dst = (buf ? sm.p2.B2l : sm.p2.B2h) + n * BST2 + q * 8;
            *(uint4*)dst = *(const uint4*)src;
        }
    }
    __syncthreads();

    // ---- epilogue1: bias + LN + GELU; build GEMM2 A-frags in registers ----
    // d1[nt][0,1] = row lg,   cols nt*8+2lt, +1
    // d1[nt][2,3] = row lg+8, same cols
    float sA = 0.f, sA2 = 0.f, sB = 0.f, sB2 = 0.f;
#pragma unroll
    for (int nt = 0; nt < 16; nt++) {
        int c0 = nt * 8 + 2 * lt;
        float v0 = d1[nt][0] + s_b1[c0];
        float v1 = d1[nt][1] + s_b1[c0 + 1];
        float v2 = d1[nt][2] + s_b1[c0];
        float v3 = d1[nt][3] + s_b1[c0 + 1];
        d1[nt][0] = v0; d1[nt][1] = v1; d1[nt][2] = v2; d1[nt][3] = v3;
        sA += v0 + v1; sA2 += v0 * v0 + v1 * v1;
        sB += v2 + v3; sB2 += v2 * v2 + v3 * v3;
    }
#pragma unroll
    for (int msk = 1; msk < 4; msk <<= 1) {
        sA  += __shfl_xor_sync(0xffffffffu, sA,  msk);
        sA2 += __shfl_xor_sync(0xffffffffu, sA2, msk);
        sB  += __shfl_xor_sync(0xffffffffu, sB,  msk);
        sB2 += __shfl_xor_sync(0xffffffffu, sB2, msk);
    }
    float muA = sA * (1.f / 128.f);
    float invA = rsqrtf(sA2 * (1.f / 128.f) - muA * muA + 1e-5f);
    float muB = sB * (1.f / 128.f);
    float invB = rsqrtf(sB2 * (1.f / 128.f) - muB * muB + 1e-5f);

    uint32_t ha[8][4], la[8][4];   // GEMM2 A-frags (hi / lo)
#pragma unroll
    for (int nt = 0; nt < 16; nt++) {
        int c0 = nt * 8 + 2 * lt;
        float gl0 = s_lng[c0], gl1 = s_lng[c0 + 1];
        float bb0 = s_lnb[c0], bb1v = s_lnb[c0 + 1];
        float h0 = (d1[nt][0] - muA) * invA * gl0 + bb0;
        float h1 = (d1[nt][1] - muA) * invA * gl1 + bb1v;
        float h2 = (d1[nt][2] - muB) * invB * gl0 + bb0;
        float h3 = (d1[nt][3] - muB) * invB * gl1 + bb1v;
        h0 = h0 * normcdff(h0); h1 = h1 * normcdff(h1);
        h2 = h2 * normcdff(h2); h3 = h3 * normcdff(h3);
        // split each into bf16 hi + lo
        float e0, e1, e2, e3;
        __nv_bfloat16 t0 = __float2bfloat16(h0); e0 = h0 - __bfloat162float(t0);
        __nv_bfloat16 t1 = __float2bfloat16(h1); e1 = h1 - __bfloat162float(t1);
        __nv_bfloat16 t2 = __float2bfloat16(h2); e2 = h2 - __bfloat162float(t2);
        __nv_bfloat16 t3 = __float2bfloat16(h3); e3 = h3 - __bfloat162float(t3);
        int s = nt >> 1, half = nt & 1;     // kstep s; a0/a1 (half=0) or a2/a3
        uint32_t* H = ha[s]; uint32_t* Lo = la[s];
        __nv_bfloat162 p01; p01.x = t0; p01.y = t1;
        __nv_bfloat162 p23; p23.x = t2; p23.y = t3;
        H[half * 2 + 0] = *reinterpret_cast<uint32_t*>(&p01);
        H[half * 2 + 1] = *reinterpret_cast<uint32_t*>(&p23);
        Lo[half * 2 + 0] = pack_bf16x2(e0, e1);
        Lo[half * 2 + 1] = pack_bf16x2(e2, e3);
    }

    // ---- GEMM2: D2[128,64] = h[128,128] x W2T, 8 ksteps x 4 pairs ---------
    float d2[8][4];
#pragma unroll
    for (int n = 0; n < 8; n++)
#pragma unroll
        for (int j = 0; j < 4; j++) d2[n][j] = 0.f;

    uint32_t baseB2h = smem_u32(sm.p2.B2h), baseB2l = smem_u32(sm.p2.B2l);
#pragma unroll
    for (int s = 0; s < 8; s++) {
#pragma unroll
        for (int p = 0; p < 4; p++) {
            uint32_t boff = ((16 * p + bN) * BST2 + s * 16 + bK) * 2;
            uint32_t bh0, bh1, bh2, bh3, bl0, bl1, bl2, bl3;
            ldsm4(bh0, bh1, bh2, bh3, baseB2h + boff);
            ldsm4(bl0, bl1, bl2, bl3, baseB2l + boff);
            mma_bf16(d2[2 * p],     ha[s], bh0, bh1);
            mma_bf16(d2[2 * p],     ha[s], bl0, bl1);
            mma_bf16(d2[2 * p],     la[s], bh0, bh1);
            mma_bf16(d2[2 * p + 1], ha[s], bh2, bh3);
            mma_bf16(d2[2 * p + 1], ha[s], bl2, bl3);
            mma_bf16(d2[2 * p + 1], la[s], bh2, bh3);
        }
    }

    // ---- epilogue2: bias + GELU + dot W3 + b3 -----------------------------
    float pA = 0.f, pB = 0.f;
#pragma unroll
    for (int nt = 0; nt < 8; nt++) {
        int c0 = nt * 8 + 2 * lt;
        float w30 = s_w3[c0], w31 = s_w3[c0 + 1];
        float x0 = d2[nt][0] + s_b2[c0];
        float x1 = d2[nt][1] + s_b2[c0 + 1];
        float x2 = d2[nt][2] + s_b2[c0];
        float x3 = d2[nt][3] + s_b2[c0 + 1];
        pA = fmaf(x0 * normcdff(x0), w30, pA);
        pA = fmaf(x1 * normcdff(x1), w31, pA);
        pB = fmaf(x2 * normcdff(x2), w30, pB);
        pB = fmaf(x3 * normcdff(x3), w31, pB);
    }
#pragma unroll
    for (int msk = 1; msk < 4; msk <<= 1) {
        pA += __shfl_xor_sync(0xffffffffu, pA, msk);
        pB += __shfl_xor_sync(0xffffffffu, pB, msk);
    }
    if (lt == 0) {
        float b3v = b3[g];
        int rA = w * 16 + lg, rB = rA + 8;
        if (rA < nE) out[tileStart + rA] = pA + b3v;
        if (rB < nE) out[tileStart + rB] = pB + b3v;
    }
}

// ---------------------------------------------------------------------------
extern "C" void kernel_launch(void* const* d_in, const int* in_sizes, int n_in,
                              void* d_out, int out_size) {
    const float* emb    = (const float*)d_in[0];
    const int*   edges  = (const int*)d_in[1];
    const int*   groups = (const int*)d_in[2];
    const float* W1     = (const float*)d_in[3];
    const float* b1     = (const float*)d_in[4];
    const float* lng    = (const float*)d_in[5];
    const float* lnb    = (const float*)d_in[6];
    const float* W2     = (const float*)d_in[7];
    const float* b2     = (const float*)d_in[8];
    const float* W3     = (const float*)d_in[9];
    const float* b3     = (const float*)d_in[10];
    float* out = (float*)d_out;

    int E = in_sizes[2];
    int embElems = in_sizes[0];
    int nChunks = (E + CHUNK - 1) / CHUNK;

    k_count<<<(nChunks + 255) / 256, 256>>>(groups, E, nChunks);
    k_scan<<<1, SCAN_T>>>(nChunks);
    k_scatter<<<(nChunks + 255) / 256, 256>>>(groups, E, nChunks);

    k_split_emb<<<(embElems + 255) / 256, 256>>>(emb, embElems);
    k_split_w1<<<(3 * 256 * 128 + 255) / 256, 256>>>(W1);
    k_split_w2<<<(3 * 128 * 64 + 255) / 256, 256>>>(W2);

    int maxTiles = (E + 127) / 128 + 3;
    k_main<<<maxTiles, 256>>>(edges, b1, lng, lnb, b2, W3, b3, out);
}

// round 13
// speedup vs baseline: 1.3596x; 1.1228x over previous
#include <cuda_runtime.h>
#include <cuda_bf16.h>
#include <math.h>
#include <stdint.h>

// Problem constants: N=100000, H=128, E=500000, G=3
#define MAX_E      600000
#define MAX_NODES  100608
#define CHUNK      128
#define MAX_CHUNKS ((MAX_E + CHUNK - 1) / CHUNK)

__device__ int d_perm[MAX_E];
__device__ int d_chunkCnt[MAX_CHUNKS * 3];
__device__ int d_chunkOff[MAX_CHUNKS * 3];
__device__ int d_groupStart[4];
__device__ int d_tileBase[4];

__device__ unsigned short d_emb_hi[MAX_NODES * 128];
__device__ unsigned short d_emb_lo[MAX_NODES * 128];
__device__ unsigned short d_w1t_hi[3 * 128 * 256];   // [g][n=128][k=256]
__device__ unsigned short d_w1t_lo[3 * 128 * 256];
__device__ unsigned short d_w2t_hi[3 * 64 * 128];    // [g][n=64][k=128]
__device__ unsigned short d_w2t_lo[3 * 64 * 128];

// ======================= helpers ============================================
__device__ __forceinline__ uint32_t smem_u32(const void* p) {
    uint32_t a;
    asm("{ .reg .u64 t; cvta.to.shared.u64 t, %1; cvt.u32.u64 %0, t; }"
        : "=r"(a) : "l"(p));
    return a;
}
__device__ __forceinline__ void ldsm4(uint32_t& r0, uint32_t& r1,
                                      uint32_t& r2, uint32_t& r3, uint32_t a) {
    asm volatile("ldmatrix.sync.aligned.m8n8.x4.shared.b16 {%0,%1,%2,%3}, [%4];"
        : "=r"(r0), "=r"(r1), "=r"(r2), "=r"(r3) : "r"(a));
}
__device__ __forceinline__ void mma_bf16(float* d, const uint32_t* a,
                                         uint32_t b0, uint32_t b1) {
    asm volatile("mma.sync.aligned.m16n8k16.row.col.f32.bf16.bf16.f32 "
        "{%0,%1,%2,%3}, {%4,%5,%6,%7}, {%8,%9}, {%0,%1,%2,%3};"
        : "+f"(d[0]), "+f"(d[1]), "+f"(d[2]), "+f"(d[3])
        : "r"(a[0]), "r"(a[1]), "r"(a[2]), "r"(a[3]), "r"(b0), "r"(b1));
}
__device__ __forceinline__ uint32_t pack_bf16x2(float x, float y) {
    __nv_bfloat162 v = __floats2bfloat162_rn(x, y);
    return *reinterpret_cast<uint32_t*>(&v);
}
#define CP16(dst, src) \
    asm volatile("cp.async.cg.shared.global [%0], [%1], 16;" \
        :: "r"(dst), "l"(src) : "memory")
#define CP_COMMIT() asm volatile("cp.async.commit_group;" ::: "memory")
#define CP_WAIT_ALL() asm volatile("cp.async.wait_group 0;" ::: "memory")

// ======================= partition (128-edge tiles) =========================
__global__ void k_count(const int* __restrict__ groups, int E, int nChunks) {
    int c = blockIdx.x * blockDim.x + threadIdx.x;
    if (c >= nChunks) return;
    int c0 = 0, c1 = 0, c2 = 0;
    int s = c * CHUNK, e = s + CHUNK; if (e > E) e = E;
    for (int i = s; i < e; i++) {
        int g = groups[i];
        c0 += (g == 0); c1 += (g == 1); c2 += (g == 2);
    }
    d_chunkCnt[c * 3 + 0] = c0; d_chunkCnt[c * 3 + 1] = c1; d_chunkCnt[c * 3 + 2] = c2;
}

#define SCAN_T 512
__global__ void k_scan(int nChunks) {
    __shared__ int sv[SCAN_T]; __shared__ int gtot[3]; __shared__ int gs[4];
    int tid = threadIdx.x;
    int per = (nChunks + SCAN_T - 1) / SCAN_T;
    int c0 = tid * per, c1 = c0 + per;
    if (c1 > nChunks) c1 = nChunks;
    if (c0 > nChunks) c0 = nChunks;
    int t[3] = {0, 0, 0};
    for (int c = c0; c < c1; c++) {
        t[0] += d_chunkCnt[c * 3]; t[1] += d_chunkCnt[c * 3 + 1]; t[2] += d_chunkCnt[c * 3 + 2];
    }
    int base[3];
    for (int g = 0; g < 3; g++) {
        sv[tid] = t[g];
        __syncthreads();
        for (int off = 1; off < SCAN_T; off <<= 1) {
            int v = (tid >= off) ? sv[tid - off] : 0;
            __syncthreads(); sv[tid] += v; __syncthreads();
        }
        base[g] = sv[tid] - t[g];
        if (tid == SCAN_T - 1) gtot[g] = sv[tid];
        __syncthreads();
    }
    if (tid == 0) {
        gs[0] = 0; gs[1] = gtot[0]; gs[2] = gtot[0] + gtot[1]; gs[3] = gs[2] + gtot[2];
        int tb = 0;
        for (int g = 0; g < 3; g++) {
            d_groupStart[g] = gs[g]; d_tileBase[g] = tb;
            tb += (gtot[g] + 127) >> 7;
        }
        d_groupStart[3] = gs[3]; d_tileBase[3] = tb;
    }
    __syncthreads();
    int run[3];
    for (int g = 0; g < 3; g++) run[g] = gs[g] + base[g];
    for (int c = c0; c < c1; c++)
        for (int g = 0; g < 3; g++) { d_chunkOff[c * 3 + g] = run[g]; run[g] += d_chunkCnt[c * 3 + g]; }
}

__global__ void k_scatter(const int* __restrict__ groups, int E, int nChunks) {
    int c = blockIdx.x * blockDim.x + threadIdx.x;
    if (c >= nChunks) return;
    int o0 = d_chunkOff[c * 3], o1 = d_chunkOff[c * 3 + 1], o2 = d_chunkOff[c * 3 + 2];
    int s = c * CHUNK, e = s + CHUNK; if (e > E) e = E;
    for (int i = s; i < e; i++) {
        int g = groups[i];
        int p = (g == 0) ? o0++ : (g == 1) ? o1++ : o2++;
        d_perm[p] = i;
    }
}

// =========================== bf16 split preps ===============================
__device__ __forceinline__ void split_bf16(float x, unsigned short& h, unsigned short& l) {
    __nv_bfloat16 hb = __float2bfloat16(x);
    float hf = __bfloat162float(hb);
    __nv_bfloat16 lb = __float2bfloat16(x - hf);
    h = __bfloat16_as_ushort(hb); l = __bfloat16_as_ushort(lb);
}
__global__ void k_split_emb(const float* __restrict__ emb, int total4) {
    int i = blockIdx.x * blockDim.x + threadIdx.x;
    if (i >= total4) return;
    float4 v = reinterpret_cast<const float4*>(emb)[i];
    ushort4 h, l;
    split_bf16(v.x, h.x, l.x); split_bf16(v.y, h.y, l.y);
    split_bf16(v.z, h.z, l.z); split_bf16(v.w, h.w, l.w);
    reinterpret_cast<ushort4*>(d_emb_hi)[i] = h;
    reinterpret_cast<ushort4*>(d_emb_lo)[i] = l;
}
__global__ void k_split_w1(const float* __restrict__ W1) {
    int i = blockIdx.x * blockDim.x + threadIdx.x;
    if (i >= 3 * 256 * 128) return;
    int g = i / (256 * 128), r = i % (256 * 128);
    int d = r / 128, h = r % 128;
    int dst = (g * 128 + h) * 256 + d;
    split_bf16(W1[i], d_w1t_hi[dst], d_w1t_lo[dst]);
}
__global__ void k_split_w2(const float* __restrict__ W2) {
    int i = blockIdx.x * blockDim.x + threadIdx.x;
    if (i >= 3 * 128 * 64) return;
    int g = i / (128 * 64), r = i % (128 * 64);
    int k = r / 64, n = r % 64;
    int dst = (g * 64 + n) * 128 + k;
    split_bf16(W2[i], d_w2t_hi[dst], d_w2t_lo[dst]);
}

// =============================== main kernel ================================
// 128-edge tile, 256 threads = 8 warps (warp w: rows w*16..w*16+15).
// GEMM1: K=256 in 16 chunks of 16, cp.async double-buffered.
// Chunk layout: 32B rows (2x16B blocks); block b of row r stored at
// r*32 + ((b ^ ((r>>2)&1))*16)  -> ldmatrix conflict-free, no padding.
// GEMM2: B2 padded rows (272B), prefetched via cp.async during epilogue1.

#define BST2 136   // B2 padded row stride in bf16 (128+8)

__global__ __launch_bounds__(256) void k_main(
    const int* __restrict__ edges,
    const float* __restrict__ b1, const float* __restrict__ lng,
    const float* __restrict__ lnb, const float* __restrict__ b2,
    const float* __restrict__ W3, const float* __restrict__ b3,
    float* __restrict__ out)
{
    __shared__ __align__(16) union {
        struct {
            unsigned short A[2][2][2048];   // [buf][hi/lo][128 rows x 16 k]
            unsigned short B[2][2][2048];
        } p1;                               // 32768 B
        struct {
            unsigned short B2h[64 * BST2]; unsigned short B2l[64 * BST2];
        } p2;                               // 34816 B
    } sm;
    __shared__ int sU[128], sV[128];
    __shared__ float s_b1[128], s_lng[128], s_lnb[128];
    __shared__ float s_b2[64], s_w3[64];

    int b = blockIdx.x;
    if (b >= d_tileBase[3]) return;
    int g = (b >= d_tileBase[1]) + (b >= d_tileBase[2]);
    int tileStart = d_groupStart[g] + (b - d_tileBase[g]) * 128;
    int nE = d_groupStart[g + 1] - tileStart;
    if (nE > 128) nE = 128;

    int tid = threadIdx.x;
    int w = tid >> 5, L = tid & 31;
    int lg = L >> 2, lt = L & 3;
    int m8 = L >> 3, r8 = L & 7;

    if (tid < 128) {
        int u = 0, v = 0;
        if (tid < nE) {
            int e = d_perm[tileStart + tid];
            u = edges[2 * e]; v = edges[2 * e + 1];
        }
        sU[tid] = u; sV[tid] = v;
        s_b1[tid]  = b1[g * 128 + tid];
        s_lng[tid] = lng[g * 128 + tid];
        s_lnb[tid] = lnb[g * 128 + tid];
    }
    if (tid < 64) { s_b2[tid] = b2[g * 64 + tid]; s_w3[tid] = W3[g * 64 + tid]; }
    __syncthreads();

    const unsigned short* w1h = d_w1t_hi + (size_t)g * 128 * 256;
    const unsigned short* w1l = d_w1t_lo + (size_t)g * 128 * 256;

    uint32_t baseA[2][2], baseB[2][2];
#pragma unroll
    for (int bu = 0; bu < 2; bu++)
#pragma unroll
        for (int hl = 0; hl < 2; hl++) {
            baseA[bu][hl] = smem_u32(&sm.p1.A[bu][hl][0]);
            baseB[bu][hl] = smem_u32(&sm.p1.B[bu][hl][0]);
        }

    // issue cp.asyncs for one K=16 chunk into buffer bu
    auto issueChunk = [&](int chunk, int bu) {
        int kb = chunk * 16;
#pragma unroll
        for (int t = 0; t < 4; t++) {
            int idx = tid + t * 256;          // 0..1023
            if (idx < 512) {                  // A: 128 rows x 2 blk x 2 hl
                int row = idx >> 2;
                int hl = (idx >> 1) & 1;
                int blk = idx & 1;
                int node = (kb < 128) ? sU[row] : sV[row];
                const unsigned short* src = (hl ? d_emb_lo : d_emb_hi)
                    + (size_t)node * 128 + (kb & 127) + blk * 8;
                uint32_t dst = baseA[bu][hl]
                    + (uint32_t)(row * 32 + ((blk ^ ((row >> 2) & 1)) << 4));
                CP16(dst, src);
            } else {                          // B: 128 n x 2 blk x 2 hl
                int i = idx - 512;
                int n = i >> 2;
                int hl = (i >> 1) & 1;
                int blk = i & 1;
                const unsigned short* src = (hl ? w1l : w1h)
                    + (size_t)n * 256 + kb + blk * 8;
                uint32_t dst = baseB[bu][hl]
                    + (uint32_t)(n * 32 + ((blk ^ ((n >> 2) & 1)) << 4));
                CP16(dst, src);
            }
        }
    };

    // ---- GEMM1: D1[128,128] -----------------------------------------------
    float d1[16][4];
#pragma unroll
    for (int n = 0; n < 16; n++)
#pragma unroll
        for (int j = 0; j < 4; j++) d1[n][j] = 0.f;

    int aRow = w * 16 + r8 + (m8 & 1) * 8;
    int aBlk = m8 >> 1;
    uint32_t aOff = (uint32_t)(aRow * 32 + ((aBlk ^ ((aRow >> 2) & 1)) << 4));
    int bN = r8 + (m8 >> 1) * 8;
    int bBlk = m8 & 1;

    issueChunk(0, 0);
    CP_COMMIT();

    for (int c = 0; c < 16; c++) {
        int bu = c & 1;
        CP_WAIT_ALL();
        __syncthreads();
        if (c + 1 < 16) { issueChunk(c + 1, (c + 1) & 1); CP_COMMIT(); }

        uint32_t ah[4], al[4];
        ldsm4(ah[0], ah[1], ah[2], ah[3], baseA[bu][0] + aOff);
        ldsm4(al[0], al[1], al[2], al[3], baseA[bu][1] + aOff);
#pragma unroll
        for (int p = 0; p < 8; p++) {
            int bRow = 16 * p + bN;
            uint32_t boff = (uint32_t)(bRow * 32 + ((bBlk ^ ((bRow >> 2) & 1)) << 4));
            uint32_t bh0, bh1, bh2, bh3, bl0, bl1, bl2, bl3;
            ldsm4(bh0, bh1, bh2, bh3, baseB[bu][0] + boff);
            ldsm4(bl0, bl1, bl2, bl3, baseB[bu][1] + boff);
            mma_bf16(d1[2 * p],     ah, bh0, bh1);
            mma_bf16(d1[2 * p],     ah, bl0, bl1);
            mma_bf16(d1[2 * p],     al, bh0, bh1);
            mma_bf16(d1[2 * p + 1], ah, bh2, bh3);
            mma_bf16(d1[2 * p + 1], ah, bl2, bl3);
            mma_bf16(d1[2 * p + 1], al, bh2, bh3);
        }
    }
    __syncthreads();   // all reads of p1 done before B2 overwrites (union)

    // ---- prefetch B2 (W2T) via cp.async; overlapped with epilogue1 --------
    {
        const unsigned short* w2h = d_w2t_hi + (size_t)g * 64 * 128;
        const unsigned short* w2l = d_w2t_lo + (size_t)g * 64 * 128;
        uint32_t b2h = smem_u32(sm.p2.B2h), b2l = smem_u32(sm.p2.B2l);
#pragma unroll
        for (int t = 0; t < 8; t++) {
            int idx = tid + t * 256;          // 0..2047
            int hl = idx >> 10, i = idx & 1023;
            int n = i >> 4, q = i & 15;
            const unsigned short* src = (hl ? w2l : w2h) + (size_t)n * 128 + q * 8;
            uint32_t dst = (hl ? b2l : b2h) + (uint32_t)(n * 272 + q * 16);
            CP16(dst, src);
        }
        CP_COMMIT();
    }

    // ---- epilogue1: bias + LN + GELU; build GEMM2 A-frags in registers ----
    float sA = 0.f, sA2 = 0.f, sB = 0.f, sB2 = 0.f;
#pragma unroll
    for (int nt = 0; nt < 16; nt++) {
        int c0 = nt * 8 + 2 * lt;
        float v0 = d1[nt][0] + s_b1[c0];
        float v1 = d1[nt][1] + s_b1[c0 + 1];
        float v2 = d1[nt][2] + s_b1[c0];
        float v3 = d1[nt][3] + s_b1[c0 + 1];
        d1[nt][0] = v0; d1[nt][1] = v1; d1[nt][2] = v2; d1[nt][3] = v3;
        sA += v0 + v1; sA2 += v0 * v0 + v1 * v1;
        sB += v2 + v3; sB2 += v2 * v2 + v3 * v3;
    }
#pragma unroll
    for (int msk = 1; msk < 4; msk <<= 1) {
        sA  += __shfl_xor_sync(0xffffffffu, sA,  msk);
        sA2 += __shfl_xor_sync(0xffffffffu, sA2, msk);
        sB  += __shfl_xor_sync(0xffffffffu, sB,  msk);
        sB2 += __shfl_xor_sync(0xffffffffu, sB2, msk);
    }
    float muA = sA * (1.f / 128.f);
    float invA = rsqrtf(sA2 * (1.f / 128.f) - muA * muA + 1e-5f);
    float muB = sB * (1.f / 128.f);
    float invB = rsqrtf(sB2 * (1.f / 128.f) - muB * muB + 1e-5f);

    uint32_t ha[8][4], la[8][4];
#pragma unroll
    for (int nt = 0; nt < 16; nt++) {
        int c0 = nt * 8 + 2 * lt;
        float gl0 = s_lng[c0], gl1 = s_lng[c0 + 1];
        float bb0 = s_lnb[c0], bb1v = s_lnb[c0 + 1];
        float h0 = (d1[nt][0] - muA) * invA * gl0 + bb0;
        float h1 = (d1[nt][1] - muA) * invA * gl1 + bb1v;
        float h2 = (d1[nt][2] - muB) * invB * gl0 + bb0;
        float h3 = (d1[nt][3] - muB) * invB * gl1 + bb1v;
        h0 = h0 * normcdff(h0); h1 = h1 * normcdff(h1);
        h2 = h2 * normcdff(h2); h3 = h3 * normcdff(h3);
        float e0, e1, e2, e3;
        __nv_bfloat16 t0 = __float2bfloat16(h0); e0 = h0 - __bfloat162float(t0);
        __nv_bfloat16 t1 = __float2bfloat16(h1); e1 = h1 - __bfloat162float(t1);
        __nv_bfloat16 t2 = __float2bfloat16(h2); e2 = h2 - __bfloat162float(t2);
        __nv_bfloat16 t3 = __float2bfloat16(h3); e3 = h3 - __bfloat162float(t3);
        int s = nt >> 1, half = nt & 1;
        __nv_bfloat162 p01; p01.x = t0; p01.y = t1;
        __nv_bfloat162 p23; p23.x = t2; p23.y = t3;
        ha[s][half * 2 + 0] = *reinterpret_cast<uint32_t*>(&p01);
        ha[s][half * 2 + 1] = *reinterpret_cast<uint32_t*>(&p23);
        la[s][half * 2 + 0] = pack_bf16x2(e0, e1);
        la[s][half * 2 + 1] = pack_bf16x2(e2, e3);
    }

    CP_WAIT_ALL();
    __syncthreads();

    // ---- GEMM2: D2[128,64] = h[128,128] x W2T -----------------------------
    float d2[8][4];
#pragma unroll
    for (int n = 0; n < 8; n++)
#pragma unroll
        for (int j = 0; j < 4; j++) d2[n][j] = 0.f;

    uint32_t baseB2h = smem_u32(sm.p2.B2h), baseB2l = smem_u32(sm.p2.B2l);
#pragma unroll
    for (int s = 0; s < 8; s++) {
#pragma unroll
        for (int p = 0; p < 4; p++) {
            uint32_t boff = (uint32_t)(((16 * p + bN) * BST2 + s * 16 + bBlk * 8) * 2);
            uint32_t bh0, bh1, bh2, bh3, bl0, bl1, bl2, bl3;
            ldsm4(bh0, bh1, bh2, bh3, baseB2h + boff);
            ldsm4(bl0, bl1, bl2, bl3, baseB2l + boff);
            mma_bf16(d2[2 * p],     ha[s], bh0, bh1);
            mma_bf16(d2[2 * p],     ha[s], bl0, bl1);
            mma_bf16(d2[2 * p],     la[s], bh0, bh1);
            mma_bf16(d2[2 * p + 1], ha[s], bh2, bh3);
            mma_bf16(d2[2 * p + 1], ha[s], bl2, bl3);
            mma_bf16(d2[2 * p + 1], la[s], bh2, bh3);
        }
    }

    // ---- epilogue2: bias + GELU + dot W3 + b3 -----------------------------
    float pA = 0.f, pB = 0.f;
#pragma unroll
    for (int nt = 0; nt < 8; nt++) {
        int c0 = nt * 8 + 2 * lt;
        float w30 = s_w3[c0], w31 = s_w3[c0 + 1];
        float x0 = d2[nt][0] + s_b2[c0];
        float x1 = d2[nt][1] + s_b2[c0 + 1];
        float x2 = d2[nt][2] + s_b2[c0];
        float x3 = d2[nt][3] + s_b2[c0 + 1];
        pA = fmaf(x0 * normcdff(x0), w30, pA);
        pA = fmaf(x1 * normcdff(x1), w31, pA);
        pB = fmaf(x2 * normcdff(x2), w30, pB);
        pB = fmaf(x3 * normcdff(x3), w31, pB);
    }
#pragma unroll
    for (int msk = 1; msk < 4; msk <<= 1) {
        pA += __shfl_xor_sync(0xffffffffu, pA, msk);
        pB += __shfl_xor_sync(0xffffffffu, pB, msk);
    }
    if (lt == 0) {
        float b3v = b3[g];
        int rA = w * 16 + lg, rB = rA + 8;
        if (rA < nE) out[tileStart + rA] = pA + b3v;
        if (rB < nE) out[tileStart + rB] = pB + b3v;
    }
}

// ---------------------------------------------------------------------------
extern "C" void kernel_launch(void* const* d_in, const int* in_sizes, int n_in,
                              void* d_out, int out_size) {
    const float* emb    = (const float*)d_in[0];
    const int*   edges  = (const int*)d_in[1];
    const int*   groups = (const int*)d_in[2];
    const float* W1     = (const float*)d_in[3];
    const float* b1     = (const float*)d_in[4];
    const float* lng    = (const float*)d_in[5];
    const float* lnb    = (const float*)d_in[6];
    const float* W2     = (const float*)d_in[7];
    const float* b2     = (const float*)d_in[8];
    const float* W3     = (const float*)d_in[9];
    const float* b3     = (const float*)d_in[10];
    float* out = (float*)d_out;

    int E = in_sizes[2];
    int embElems = in_sizes[0];
    int nChunks = (E + CHUNK - 1) / CHUNK;

    k_count<<<(nChunks + 255) / 256, 256>>>(groups, E, nChunks);
    k_scan<<<1, SCAN_T>>>(nChunks);
    k_scatter<<<(nChunks + 255) / 256, 256>>>(groups, E, nChunks);

    int total4 = embElems / 4;
    k_split_emb<<<(total4 + 255) / 256, 256>>>(emb, total4);
    k_split_w1<<<(3 * 256 * 128 + 255) / 256, 256>>>(W1);
    k_split_w2<<<(3 * 128 * 64 + 255) / 256, 256>>>(W2);

    int maxTiles = (E + 127) / 128 + 3;
    k_main<<<maxTiles, 256>>>(edges, b1, lng, lnb, b2, W3, b3, out);
}